// round 6
// baseline (speedup 1.0000x reference)
#include <cuda_runtime.h>
#include <cuda_bf16.h>
#include <cstdint>
#include <cmath>

#define I_DIM 512
#define H_DIM 512
#define KTOT  1024
#define NTOT  1024
#define BATCH 65536

// ---------------------------------------------------------------------------
// Device scratch
// W2: u4 index = ((nb*64 + kb)*2 + term)*32 + lane   nb: 16-col block, kb: k16 block
// ---------------------------------------------------------------------------
__device__ uint4 g_W2[(size_t)64 * 64 * 2 * 32];     // 4 MB
__device__ float g_C[(size_t)BATCH * NTOT];          // 256 MB

__device__ __forceinline__ uint32_t smem_u32(const void* p) {
    uint32_t a;
    asm("{ .reg .u64 t; cvta.to.shared.u64 t, %1; cvt.u32.u64 %0, t; }"
        : "=r"(a) : "l"(p));
    return a;
}
__device__ __forceinline__ uint32_t pack_bf2(float a, float b) {
    __nv_bfloat16 ha = __float2bfloat16(a);
    __nv_bfloat16 hb = __float2bfloat16(b);
    return (uint32_t)__bfloat16_as_ushort(ha) |
           ((uint32_t)__bfloat16_as_ushort(hb) << 16);
}
__device__ __forceinline__ float bf_hi(float v) {
    return __bfloat162float(__float2bfloat16(v));
}
__device__ __forceinline__ void mma16816(float* c, const uint4& a,
                                         uint32_t b0, uint32_t b1) {
    asm volatile(
        "mma.sync.aligned.m16n8k16.row.col.f32.bf16.bf16.f32 "
        "{%0,%1,%2,%3}, {%4,%5,%6,%7}, {%8,%9}, {%0,%1,%2,%3};"
        : "+f"(c[0]), "+f"(c[1]), "+f"(c[2]), "+f"(c[3])
        : "r"(a.x), "r"(a.y), "r"(a.z), "r"(a.w), "r"(b0), "r"(b1));
}
#define CP_ASYNC16(dst, src) \
    asm volatile("cp.async.cg.shared.global [%0], [%1], 16;" \
                 :: "r"(dst), "l"(src) : "memory")
#define CP_COMMIT() asm volatile("cp.async.commit_group;" ::: "memory")
#define CP_WAIT2()  asm volatile("cp.async.wait_group 2;" ::: "memory")
#define LDS128(v, addr) \
    asm volatile("ld.shared.v4.u32 {%0,%1,%2,%3}, [%4];" \
        : "=r"((v).x), "=r"((v).y), "=r"((v).z), "=r"((v).w) : "r"(addr))
#define STS128(addr, v) \
    asm volatile("st.shared.v4.u32 [%0], {%1,%2,%3,%4};" \
        :: "r"(addr), "r"((v).x), "r"((v).y), "r"((v).z), "r"((v).w) : "memory")

// ---------------------------------------------------------------------------
// Pack W into fragment-linear hi/lo bf16 tiles.
// ---------------------------------------------------------------------------
__device__ __forceinline__ float w_at(const float* W_in, const float* W_rec,
                                      const float* W_tau, int n, int k) {
    if (n < H_DIM) return W_tau[n * KTOT + k];
    int m = n - H_DIM;
    return (k < I_DIM) ? W_in[m * I_DIM + k] : W_rec[m * H_DIM + (k - I_DIM)];
}

__global__ void pack_w_kernel(const float* __restrict__ W_in,
                              const float* __restrict__ W_rec,
                              const float* __restrict__ W_tau) {
    int t = blockIdx.x * blockDim.x + threadIdx.x;
    int lane = t & 31;
    int idx = t >> 5;
    int kb = idx & 63;
    int nb = idx >> 6;

    int n0 = nb * 16 + (lane >> 2);
    int k0 = kb * 16 + (lane & 3) * 2;

    float v[8];
    v[0] = w_at(W_in, W_rec, W_tau, n0,     k0);
    v[1] = w_at(W_in, W_rec, W_tau, n0,     k0 + 1);
    v[2] = w_at(W_in, W_rec, W_tau, n0,     k0 + 8);
    v[3] = w_at(W_in, W_rec, W_tau, n0,     k0 + 9);
    v[4] = w_at(W_in, W_rec, W_tau, n0 + 8, k0);
    v[5] = w_at(W_in, W_rec, W_tau, n0 + 8, k0 + 1);
    v[6] = w_at(W_in, W_rec, W_tau, n0 + 8, k0 + 8);
    v[7] = w_at(W_in, W_rec, W_tau, n0 + 8, k0 + 9);

    uint4 hi, lo;
    hi.x = pack_bf2(v[0], v[1]); hi.y = pack_bf2(v[2], v[3]);
    hi.z = pack_bf2(v[4], v[5]); hi.w = pack_bf2(v[6], v[7]);
    lo.x = pack_bf2(v[0] - bf_hi(v[0]), v[1] - bf_hi(v[1]));
    lo.y = pack_bf2(v[2] - bf_hi(v[2]), v[3] - bf_hi(v[3]));
    lo.z = pack_bf2(v[4] - bf_hi(v[4]), v[5] - bf_hi(v[5]));
    lo.w = pack_bf2(v[6] - bf_hi(v[6]), v[7] - bf_hi(v[7]));

    size_t base = ((size_t)(nb * 64 + kb) * 2) * 32 + lane;
    g_W2[base]      = hi;
    g_W2[base + 32] = lo;
}

// ---------------------------------------------------------------------------
// GEMM: CTA tile 128x256, warp tile 64x64 (2x4 warps), BK=32.
// A: fp32 LDG (2-iter prefetch) -> in-kernel bf16 hi/lo split -> double-buffered smem
// B: 4-stage cp.async pipeline from pre-packed g_W2
// smem: abuf[2] 16KB each @ 0, 16384 ; B stages 32KB each @ 32768 + s*32768
// ---------------------------------------------------------------------------
#define B_STAGE 32768
#define SMEM_REQ (32768 + 4*32768)

__global__ __launch_bounds__(256)
void gemm_mma_kernel(const float* __restrict__ x, const float* __restrict__ hin) {
    extern __shared__ char smem[];
    const uint32_t sbase = smem_u32(smem);

    const int tid  = threadIdx.x;
    const int wid  = tid >> 5;
    const int lane = tid & 31;
    const int bn = blockIdx.x;            // 0..3
    const int bm = blockIdx.y;            // 0..511
    const int wm = wid & 1;               // warp m (2)
    const int wn = wid >> 1;              // warp n (4)

    // ---- B cp.async mapping: 2048 chunks/stage, 8 per thread ----
    uint32_t boff[8], bsoff[8];
#pragma unroll
    for (int j = 0; j < 8; j++) {
        int c = tid + j * 256;
        int cl   = c & 31;
        int nb   = (c >> 5) & 15;
        int term = (c >> 9) & 1;
        int kb   = (c >> 10) & 1;
        int nbg = bn * 16 + nb;
        boff[j]  = (uint32_t)(nbg * 4096 + kb * 64 + term * 32 + cl);
        bsoff[j] = (uint32_t)(32768 + c * 16);   // includes B-region base
    }

    // ---- A fragment-producer mapping: thread -> (mb, plane), both kb ----
    const int plane = tid & 31;
    const int amb   = (tid >> 5) & 7;
    const size_t arow = (size_t)bm * 128 + amb * 16 + (plane >> 2);
    const int acq   = (plane & 3) * 2;

    float2 rA[8];   // A fp32 for one iter: [kb][4 float2]
#define LDA(j) do { \
        const float* src_ = ((j) < 16 ? x : hin) + (((j) & 15) * 32); \
        const float* p0_ = src_ + arow * 512; \
        const float* p8_ = p0_ + 8 * 512; \
        _Pragma("unroll") \
        for (int kb_ = 0; kb_ < 2; kb_++) { \
            int ck_ = kb_ * 16 + acq; \
            rA[kb_*4+0] = *(const float2*)(p0_ + ck_); \
            rA[kb_*4+1] = *(const float2*)(p8_ + ck_); \
            rA[kb_*4+2] = *(const float2*)(p0_ + ck_ + 8); \
            rA[kb_*4+3] = *(const float2*)(p8_ + ck_ + 8); \
        } } while (0)

#define CVT_STS(buf) do { \
        uint32_t ab_ = sbase + (buf) * 16384; \
        _Pragma("unroll") \
        for (int kb_ = 0; kb_ < 2; kb_++) { \
            uint4 hi_, lo_; \
            float2 e0 = rA[kb_*4+0], e1 = rA[kb_*4+1], e2 = rA[kb_*4+2], e3 = rA[kb_*4+3]; \
            hi_.x = pack_bf2(e0.x, e0.y); hi_.y = pack_bf2(e1.x, e1.y); \
            hi_.z = pack_bf2(e2.x, e2.y); hi_.w = pack_bf2(e3.x, e3.y); \
            lo_.x = pack_bf2(e0.x - bf_hi(e0.x), e0.y - bf_hi(e0.y)); \
            lo_.y = pack_bf2(e1.x - bf_hi(e1.x), e1.y - bf_hi(e1.y)); \
            lo_.z = pack_bf2(e2.x - bf_hi(e2.x), e2.y - bf_hi(e2.y)); \
            lo_.w = pack_bf2(e3.x - bf_hi(e3.x), e3.y - bf_hi(e3.y)); \
            STS128(ab_ + (uint32_t)(((kb_*2 + 0)*8 + amb)*512) + plane*16, hi_); \
            STS128(ab_ + (uint32_t)(((kb_*2 + 1)*8 + amb)*512) + plane*16, lo_); \
        } } while (0)

    float acc[4][8][4];
#pragma unroll
    for (int a = 0; a < 4; a++)
#pragma unroll
        for (int b = 0; b < 8; b++)
#pragma unroll
            for (int d = 0; d < 4; d++) acc[a][b][d] = 0.f;

    // ---- prologue ----
    LDA(0);
    CVT_STS(0);
    LDA(1);
#pragma unroll
    for (int s = 0; s < 3; s++) {
#pragma unroll
        for (int j = 0; j < 8; j++)
            CP_ASYNC16(sbase + s * B_STAGE + bsoff[j],
                       g_W2 + (size_t)boff[j] + (size_t)s * 128);
        CP_COMMIT();
    }

    for (int i = 0; i < 32; i++) {
        CP_WAIT2();
        __syncthreads();

        // cp.async B stage i+3  (FIX: bsoff already carries the +32768 region base)
        if (i + 3 < 32) {
            uint32_t dst = sbase + ((i + 3) & 3) * B_STAGE;
#pragma unroll
            for (int j = 0; j < 8; j++)
                CP_ASYNC16(dst + bsoff[j],
                           g_W2 + (size_t)boff[j] + (size_t)(i + 3) * 128);
        }
        CP_COMMIT();

        // convert+store A for iter i+1 (regs loaded last iter); prefetch iter i+2
        if (i + 1 < 32) CVT_STS((i + 1) & 1);
        if (i + 2 < 32) LDA(i + 2);

        const uint32_t ab = sbase + (i & 1) * 16384;
        const uint32_t st = sbase + 32768 + (i & 3) * B_STAGE;
#pragma unroll
        for (int kb = 0; kb < 2; kb++) {
            uint4 ah[4], al[4];
#pragma unroll
            for (int mt = 0; mt < 4; mt++) {
                int mb = wm * 4 + mt;
                LDS128(ah[mt], ab + (uint32_t)(((kb * 2 + 0) * 8 + mb) * 512) + lane * 16);
                LDS128(al[mt], ab + (uint32_t)(((kb * 2 + 1) * 8 + mb) * 512) + lane * 16);
            }
#pragma unroll
            for (int q = 0; q < 4; q++) {
                int nb = wn * 4 + q;
                uint4 bh, bl;
                LDS128(bh, st + (uint32_t)(((kb * 2 + 0) * 16 + nb) * 512) + lane * 16);
                LDS128(bl, st + (uint32_t)(((kb * 2 + 1) * 16 + nb) * 512) + lane * 16);
#pragma unroll
                for (int term = 0; term < 3; term++) {
#pragma unroll
                    for (int mt = 0; mt < 4; mt++) {
#pragma unroll
                        for (int p = 0; p < 2; p++) {
                            const uint4& A = (term == 2) ? al[mt] : ah[mt];
                            const uint4& B = (term == 1) ? bl : bh;
                            uint32_t b0 = p ? B.z : B.x;
                            uint32_t b1 = p ? B.w : B.y;
                            mma16816(acc[mt][q * 2 + p], A, b0, b1);
                        }
                    }
                }
            }
        }
    }

    // ---- store C ----
    const int g  = lane >> 2;
    const int tg = lane & 3;
#pragma unroll
    for (int mt = 0; mt < 4; mt++) {
        int row = bm * 128 + wm * 64 + mt * 16 + g;
#pragma unroll
        for (int nn = 0; nn < 8; nn++) {
            int col = bn * 256 + wn * 64 + nn * 8 + tg * 2;
            float2* p0 = (float2*)(g_C + (size_t)row * NTOT + col);
            float2* p1 = (float2*)(g_C + (size_t)(row + 8) * NTOT + col);
            *p0 = make_float2(acc[mt][nn][0], acc[mt][nn][1]);
            *p1 = make_float2(acc[mt][nn][2], acc[mt][nn][3]);
        }
    }
}

// ---------------------------------------------------------------------------
// Epilogue: 2 rows / 256-thread block, float4 vectorized (4 elems/thread).
// ---------------------------------------------------------------------------
__global__ __launch_bounds__(256)
void epilogue_kernel(const float* __restrict__ h,
                     const float* __restrict__ b_in, const float* __restrict__ b_tau,
                     const float* __restrict__ gamma, const float* __restrict__ beta,
                     float* __restrict__ out_h, float* __restrict__ out_tau) {
    const int tid = threadIdx.x;
    const int r   = tid >> 7;
    const int t   = tid & 127;
    const size_t row = (size_t)blockIdx.x * 2 + r;

    float4 vt = *((const float4*)(g_C + row * NTOT) + t);
    float4 vf = *((const float4*)(g_C + row * NTOT + 512) + t);
    float4 vh = *((const float4*)(h + row * H_DIM) + t);
    float4 bt = ((const float4*)b_tau)[t];
    float4 bi = ((const float4*)b_in)[t];

    float y[4], tau[4];
    {
        const float* pt = &vt.x; const float* pf = &vf.x;
        const float* ph = &vh.x; const float* pbt = &bt.x; const float* pbi = &bi.x;
#pragma unroll
        for (int c = 0; c < 4; c++) {
            float sig = 1.0f / (1.0f + __expf(-(pt[c] + pbt[c])));
            tau[c] = 0.5f + 4.5f * sig;
            float f = tanhf(pf[c] + pbi[c]);
            y[c] = ph[c] + 0.1f * (f - ph[c]) / tau[c];
        }
    }

    float s = y[0] + y[1] + y[2] + y[3];
    float s2 = y[0]*y[0] + y[1]*y[1] + y[2]*y[2] + y[3]*y[3];

    __shared__ float2 red[8];
#pragma unroll
    for (int off = 16; off > 0; off >>= 1) {
        s  += __shfl_xor_sync(0xffffffffu, s, off);
        s2 += __shfl_xor_sync(0xffffffffu, s2, off);
    }
    int warp = tid >> 5;
    if ((tid & 31) == 0) red[warp] = make_float2(s, s2);
    __syncthreads();

    int wb = r * 4;
    float S  = red[wb].x + red[wb+1].x + red[wb+2].x + red[wb+3].x;
    float S2 = red[wb].y + red[wb+1].y + red[wb+2].y + red[wb+3].y;
    float mu  = S * (1.0f / H_DIM);
    float var = S2 * (1.0f / H_DIM) - mu * mu;
    float inv = rsqrtf(var + 1e-5f);

    float4 g4 = ((const float4*)gamma)[t];
    float4 be = ((const float4*)beta)[t];
    float4 oh, ot;
    oh.x = (y[0] - mu) * inv * g4.x + be.x;
    oh.y = (y[1] - mu) * inv * g4.y + be.y;
    oh.z = (y[2] - mu) * inv * g4.z + be.z;
    oh.w = (y[3] - mu) * inv * g4.w + be.w;
    ot.x = tau[0]; ot.y = tau[1]; ot.z = tau[2]; ot.w = tau[3];

    *((float4*)(out_h + row * H_DIM) + t) = oh;
    *((float4*)(out_tau + row * H_DIM) + t) = ot;
}

// ---------------------------------------------------------------------------
extern "C" void kernel_launch(void* const* d_in, const int* in_sizes, int n_in,
                              void* d_out, int out_size) {
    const float* x     = (const float*)d_in[0];
    const float* h     = (const float*)d_in[1];
    const float* W_in  = (const float*)d_in[2];
    const float* b_in  = (const float*)d_in[3];
    const float* W_rec = (const float*)d_in[4];
    const float* W_tau = (const float*)d_in[5];
    const float* b_tau = (const float*)d_in[6];
    const float* gamma = (const float*)d_in[7];
    const float* beta  = (const float*)d_in[8];

    const int B = in_sizes[0] / I_DIM;    // 65536

    float* out = (float*)d_out;
    float* out_h   = out;
    float* out_tau = out + (size_t)B * H_DIM;

    pack_w_kernel<<<512, 256>>>(W_in, W_rec, W_tau);

    cudaFuncSetAttribute(gemm_mma_kernel,
                         cudaFuncAttributeMaxDynamicSharedMemorySize, SMEM_REQ);
    dim3 ggrid(NTOT / 256, B / 128);      // (4, 512)
    gemm_mma_kernel<<<ggrid, 256, SMEM_REQ>>>(x, h);

    epilogue_kernel<<<B / 2, 256>>>(h, b_in, b_tau, gamma, beta, out_h, out_tau);
}

// round 7
// speedup vs baseline: 1.1149x; 1.1149x over previous
#include <cuda_runtime.h>
#include <cuda_bf16.h>
#include <cstdint>
#include <cmath>

#define I_DIM 512
#define H_DIM 512
#define KTOT  1024
#define NTOT  1024
#define BATCH 65536

// ---------------------------------------------------------------------------
// Device scratch
// A2: u4 index = ((rb*64 + kb)*2 + term)*32 + lane   rb: 16-row block, kb: k16 block
// W2: u4 index = ((nb*64 + kb)*2 + term)*32 + lane   nb: 16-col block
// ---------------------------------------------------------------------------
__device__ uint4 g_A2[(size_t)4096 * 64 * 2 * 32];   // 256 MB
__device__ uint4 g_W2[(size_t)64 * 64 * 2 * 32];     // 4 MB
__device__ float g_C[(size_t)BATCH * NTOT];          // 256 MB

__device__ __forceinline__ uint32_t smem_u32(const void* p) {
    uint32_t a;
    asm("{ .reg .u64 t; cvta.to.shared.u64 t, %1; cvt.u32.u64 %0, t; }"
        : "=r"(a) : "l"(p));
    return a;
}
__device__ __forceinline__ uint32_t pack_bf2(float a, float b) {
    __nv_bfloat16 ha = __float2bfloat16(a);
    __nv_bfloat16 hb = __float2bfloat16(b);
    return (uint32_t)__bfloat16_as_ushort(ha) |
           ((uint32_t)__bfloat16_as_ushort(hb) << 16);
}
__device__ __forceinline__ float bf_hi(float v) {
    return __bfloat162float(__float2bfloat16(v));
}
__device__ __forceinline__ void mma16816(float* c, const uint4& a,
                                         uint32_t b0, uint32_t b1) {
    asm volatile(
        "mma.sync.aligned.m16n8k16.row.col.f32.bf16.bf16.f32 "
        "{%0,%1,%2,%3}, {%4,%5,%6,%7}, {%8,%9}, {%0,%1,%2,%3};"
        : "+f"(c[0]), "+f"(c[1]), "+f"(c[2]), "+f"(c[3])
        : "r"(a.x), "r"(a.y), "r"(a.z), "r"(a.w), "r"(b0), "r"(b1));
}
#define CP_ASYNC16(dst, src) \
    asm volatile("cp.async.cg.shared.global [%0], [%1], 16;" \
                 :: "r"(dst), "l"(src) : "memory")
#define CP_COMMIT() asm volatile("cp.async.commit_group;" ::: "memory")
#define CP_WAIT1()  asm volatile("cp.async.wait_group 1;" ::: "memory")

// ---------------------------------------------------------------------------
// Pack W into fragment-linear hi/lo bf16 tiles.
// ---------------------------------------------------------------------------
__device__ __forceinline__ float w_at(const float* W_in, const float* W_rec,
                                      const float* W_tau, int n, int k) {
    if (n < H_DIM) return W_tau[n * KTOT + k];
    int m = n - H_DIM;
    return (k < I_DIM) ? W_in[m * I_DIM + k] : W_rec[m * H_DIM + (k - I_DIM)];
}

__global__ void pack_w_kernel(const float* __restrict__ W_in,
                              const float* __restrict__ W_rec,
                              const float* __restrict__ W_tau) {
    int t = blockIdx.x * blockDim.x + threadIdx.x;
    int lane = t & 31;
    int idx = t >> 5;
    int kb = idx & 63;
    int nb = idx >> 6;

    int n0 = nb * 16 + (lane >> 2);
    int k0 = kb * 16 + (lane & 3) * 2;

    float v[8];
    v[0] = w_at(W_in, W_rec, W_tau, n0,     k0);
    v[1] = w_at(W_in, W_rec, W_tau, n0,     k0 + 1);
    v[2] = w_at(W_in, W_rec, W_tau, n0,     k0 + 8);
    v[3] = w_at(W_in, W_rec, W_tau, n0,     k0 + 9);
    v[4] = w_at(W_in, W_rec, W_tau, n0 + 8, k0);
    v[5] = w_at(W_in, W_rec, W_tau, n0 + 8, k0 + 1);
    v[6] = w_at(W_in, W_rec, W_tau, n0 + 8, k0 + 8);
    v[7] = w_at(W_in, W_rec, W_tau, n0 + 8, k0 + 9);

    uint4 hi, lo;
    hi.x = pack_bf2(v[0], v[1]); hi.y = pack_bf2(v[2], v[3]);
    hi.z = pack_bf2(v[4], v[5]); hi.w = pack_bf2(v[6], v[7]);
    lo.x = pack_bf2(v[0] - bf_hi(v[0]), v[1] - bf_hi(v[1]));
    lo.y = pack_bf2(v[2] - bf_hi(v[2]), v[3] - bf_hi(v[3]));
    lo.z = pack_bf2(v[4] - bf_hi(v[4]), v[5] - bf_hi(v[5]));
    lo.w = pack_bf2(v[6] - bf_hi(v[6]), v[7] - bf_hi(v[7]));

    size_t base = ((size_t)(nb * 64 + kb) * 2) * 32 + lane;
    g_W2[base]      = hi;
    g_W2[base + 32] = lo;
}

// ---------------------------------------------------------------------------
// Split A = [x | h] into fragment-linear hi/lo bf16 tiles.
// ---------------------------------------------------------------------------
__global__ __launch_bounds__(256)
void split_a_kernel(const float* __restrict__ x, const float* __restrict__ h) {
    const int rb = blockIdx.x;            // 0..4095
    const int tid = threadIdx.x;
    const int wid = tid >> 5;
    const int lane = tid & 31;

    const int r0 = lane >> 2;
    const int cq = (lane & 3) * 2;
    const size_t rowA = (size_t)rb * 16 + r0;
    const size_t rowB = rowA + 8;

#pragma unroll
    for (int j = 0; j < 8; j++) {
        int kb = wid * 8 + j;             // 0..63
        int kg = kb * 16 + cq;
        const float* srcA;
        const float* srcB;
        if (kb < 32) { srcA = x + rowA * I_DIM + kg;          srcB = x + rowB * I_DIM + kg; }
        else         { srcA = h + rowA * H_DIM + (kg - 512);  srcB = h + rowB * H_DIM + (kg - 512); }

        float a0 = srcA[0], a1 = srcA[1], a2 = srcA[8], a3 = srcA[9];
        float b0 = srcB[0], b1 = srcB[1], b2 = srcB[8], b3 = srcB[9];

        uint4 hi, lo;
        hi.x = pack_bf2(a0, a1); hi.y = pack_bf2(b0, b1);
        hi.z = pack_bf2(a2, a3); hi.w = pack_bf2(b2, b3);
        lo.x = pack_bf2(a0 - bf_hi(a0), a1 - bf_hi(a1));
        lo.y = pack_bf2(b0 - bf_hi(b0), b1 - bf_hi(b1));
        lo.z = pack_bf2(a2 - bf_hi(a2), a3 - bf_hi(a3));
        lo.w = pack_bf2(b2 - bf_hi(b2), b3 - bf_hi(b3));

        size_t base = ((size_t)(rb * 64 + kb) * 2) * 32 + lane;
        g_A2[base]      = hi;
        g_A2[base + 32] = lo;
    }
}

// ---------------------------------------------------------------------------
// GEMM: CTA tile 128x128, warp tile 64x32 (2x4 warps), BK=32,
// 3-stage cp.async pipeline (96KB smem -> 2 CTAs/SM).
// ---------------------------------------------------------------------------
#define STAGE_BYTES 32768
#define N_STAGES 3

__global__ __launch_bounds__(256)
void gemm_mma_kernel() {
    extern __shared__ char smem[];
    const uint32_t sbase = smem_u32(smem);

    const int tid  = threadIdx.x;
    const int wid  = tid >> 5;
    const int lane = tid & 31;
    const int bn = blockIdx.x;            // 0..7
    const int bm = blockIdx.y;            // 0..511

    uint32_t soff[8];
    const uint4* gptr[8];
#pragma unroll
    for (int j = 0; j < 8; j++) {
        int c = tid + j * 256;            // chunk id 0..2047
        int cl   = c & 31;
        int blk  = (c >> 5) & 7;          // mb or nb
        int term = (c >> 8) & 1;
        int kb   = (c >> 9) & 1;
        if (c < 1024) {
            int rb = bm * 8 + blk;
            gptr[j] = g_A2 + (((size_t)(rb * 64 + kb) * 2 + term) * 32 + cl);
        } else {
            int nb = bn * 8 + blk;
            gptr[j] = g_W2 + (((size_t)(nb * 64 + kb) * 2 + term) * 32 + cl);
        }
        soff[j] = (uint32_t)(c * 16);
    }

    float acc[4][4][4];
#pragma unroll
    for (int a = 0; a < 4; a++)
#pragma unroll
        for (int b = 0; b < 4; b++)
#pragma unroll
            for (int d = 0; d < 4; d++) acc[a][b][d] = 0.f;

#pragma unroll
    for (int s = 0; s < 2; s++) {
#pragma unroll
        for (int j = 0; j < 8; j++)
            CP_ASYNC16(sbase + s * STAGE_BYTES + soff[j], gptr[j] + (size_t)s * 128);
        CP_COMMIT();
    }

    const int mbB = (wid & 1) * 4;
    const int nbB = (wid >> 1) * 2;

    for (int i = 0; i < 32; i++) {
        CP_WAIT1();
        __syncthreads();

        if (i + 2 < 32) {
            uint32_t sb = sbase + ((i + 2) % N_STAGES) * STAGE_BYTES;
#pragma unroll
            for (int j = 0; j < 8; j++)
                CP_ASYNC16(sb + soff[j], gptr[j] + (size_t)(i + 2) * 128);
        }
        CP_COMMIT();

        const uint32_t st = sbase + (i % N_STAGES) * STAGE_BYTES;
#pragma unroll
        for (int kb = 0; kb < 2; kb++) {
            uint4 ah[4], al[4], bh[2], bl[2];
#pragma unroll
            for (int mb = 0; mb < 4; mb++) {
                uint32_t ahi = st + ((kb * 2 + 0) * 8 + mbB + mb) * 512 + lane * 16;
                uint32_t alo = st + ((kb * 2 + 1) * 8 + mbB + mb) * 512 + lane * 16;
                asm volatile("ld.shared.v4.u32 {%0,%1,%2,%3}, [%4];"
                    : "=r"(ah[mb].x), "=r"(ah[mb].y), "=r"(ah[mb].z), "=r"(ah[mb].w) : "r"(ahi));
                asm volatile("ld.shared.v4.u32 {%0,%1,%2,%3}, [%4];"
                    : "=r"(al[mb].x), "=r"(al[mb].y), "=r"(al[mb].z), "=r"(al[mb].w) : "r"(alo));
            }
#pragma unroll
            for (int p = 0; p < 2; p++) {
                uint32_t bhi = st + 16384 + ((kb * 2 + 0) * 8 + nbB + p) * 512 + lane * 16;
                uint32_t blo = st + 16384 + ((kb * 2 + 1) * 8 + nbB + p) * 512 + lane * 16;
                asm volatile("ld.shared.v4.u32 {%0,%1,%2,%3}, [%4];"
                    : "=r"(bh[p].x), "=r"(bh[p].y), "=r"(bh[p].z), "=r"(bh[p].w) : "r"(bhi));
                asm volatile("ld.shared.v4.u32 {%0,%1,%2,%3}, [%4];"
                    : "=r"(bl[p].x), "=r"(bl[p].y), "=r"(bl[p].z), "=r"(bl[p].w) : "r"(blo));
            }
#pragma unroll
            for (int term = 0; term < 3; term++) {
#pragma unroll
                for (int mt = 0; mt < 4; mt++) {
#pragma unroll
                    for (int nt = 0; nt < 4; nt++) {
                        const uint4& A = (term == 2) ? al[mt] : ah[mt];
                        const uint4& B = (term == 1) ? bl[nt >> 1] : bh[nt >> 1];
                        uint32_t b0 = (nt & 1) ? B.z : B.x;
                        uint32_t b1 = (nt & 1) ? B.w : B.y;
                        mma16816(acc[mt][nt], A, b0, b1);
                    }
                }
            }
        }
        __syncthreads();
    }

    const int g  = lane >> 2;
    const int tg = lane & 3;
#pragma unroll
    for (int mt = 0; mt < 4; mt++) {
        int row = bm * 128 + (wid & 1) * 64 + mt * 16 + g;
#pragma unroll
        for (int nt = 0; nt < 4; nt++) {
            int col = bn * 128 + (wid >> 1) * 32 + nt * 8 + tg * 2;
            float2* p0 = (float2*)(g_C + (size_t)row * NTOT + col);
            float2* p1 = (float2*)(g_C + (size_t)(row + 8) * NTOT + col);
            *p0 = make_float2(acc[mt][nt][0], acc[mt][nt][1]);
            *p1 = make_float2(acc[mt][nt][2], acc[mt][nt][3]);
        }
    }
}

// ---------------------------------------------------------------------------
// Epilogue: 2 rows / 256-thread block, float4 vectorized (4 elems/thread).
// ---------------------------------------------------------------------------
__global__ __launch_bounds__(256)
void epilogue_kernel(const float* __restrict__ h,
                     const float* __restrict__ b_in, const float* __restrict__ b_tau,
                     const float* __restrict__ gamma, const float* __restrict__ beta,
                     float* __restrict__ out_h, float* __restrict__ out_tau) {
    const int tid = threadIdx.x;
    const int r   = tid >> 7;
    const int t   = tid & 127;
    const size_t row = (size_t)blockIdx.x * 2 + r;

    float4 vt = *((const float4*)(g_C + row * NTOT) + t);
    float4 vf = *((const float4*)(g_C + row * NTOT + 512) + t);
    float4 vh = *((const float4*)(h + row * H_DIM) + t);
    float4 bt = ((const float4*)b_tau)[t];
    float4 bi = ((const float4*)b_in)[t];

    float y[4], tau[4];
    {
        const float* pt = &vt.x; const float* pf = &vf.x;
        const float* ph = &vh.x; const float* pbt = &bt.x; const float* pbi = &bi.x;
#pragma unroll
        for (int c = 0; c < 4; c++) {
            float sig = 1.0f / (1.0f + __expf(-(pt[c] + pbt[c])));
            tau[c] = 0.5f + 4.5f * sig;
            float f = tanhf(pf[c] + pbi[c]);
            y[c] = ph[c] + 0.1f * (f - ph[c]) / tau[c];
        }
    }

    float s = y[0] + y[1] + y[2] + y[3];
    float s2 = y[0]*y[0] + y[1]*y[1] + y[2]*y[2] + y[3]*y[3];

    __shared__ float2 red[8];
#pragma unroll
    for (int off = 16; off > 0; off >>= 1) {
        s  += __shfl_xor_sync(0xffffffffu, s, off);
        s2 += __shfl_xor_sync(0xffffffffu, s2, off);
    }
    int warp = tid >> 5;
    if ((tid & 31) == 0) red[warp] = make_float2(s, s2);
    __syncthreads();

    int wb = r * 4;
    float S  = red[wb].x + red[wb+1].x + red[wb+2].x + red[wb+3].x;
    float S2 = red[wb].y + red[wb+1].y + red[wb+2].y + red[wb+3].y;
    float mu  = S * (1.0f / H_DIM);
    float var = S2 * (1.0f / H_DIM) - mu * mu;
    float inv = rsqrtf(var + 1e-5f);

    float4 g4 = ((const float4*)gamma)[t];
    float4 be = ((const float4*)beta)[t];
    float4 oh, ot;
    oh.x = (y[0] - mu) * inv * g4.x + be.x;
    oh.y = (y[1] - mu) * inv * g4.y + be.y;
    oh.z = (y[2] - mu) * inv * g4.z + be.z;
    oh.w = (y[3] - mu) * inv * g4.w + be.w;
    ot.x = tau[0]; ot.y = tau[1]; ot.z = tau[2]; ot.w = tau[3];

    *((float4*)(out_h + row * H_DIM) + t) = oh;
    *((float4*)(out_tau + row * H_DIM) + t) = ot;
}

// ---------------------------------------------------------------------------
extern "C" void kernel_launch(void* const* d_in, const int* in_sizes, int n_in,
                              void* d_out, int out_size) {
    const float* x     = (const float*)d_in[0];
    const float* h     = (const float*)d_in[1];
    const float* W_in  = (const float*)d_in[2];
    const float* b_in  = (const float*)d_in[3];
    const float* W_rec = (const float*)d_in[4];
    const float* W_tau = (const float*)d_in[5];
    const float* b_tau = (const float*)d_in[6];
    const float* gamma = (const float*)d_in[7];
    const float* beta  = (const float*)d_in[8];

    const int B = in_sizes[0] / I_DIM;    // 65536

    float* out = (float*)d_out;
    float* out_h   = out;
    float* out_tau = out + (size_t)B * H_DIM;

    pack_w_kernel<<<512, 256>>>(W_in, W_rec, W_tau);
    split_a_kernel<<<B / 16, 256>>>(x, h);

    cudaFuncSetAttribute(gemm_mma_kernel,
                         cudaFuncAttributeMaxDynamicSharedMemorySize,
                         N_STAGES * STAGE_BYTES);
    dim3 ggrid(NTOT / 128, B / 128);      // (8, 512)
    gemm_mma_kernel<<<ggrid, 256, N_STAGES * STAGE_BYTES>>>();

    epilogue_kernel<<<B / 2, 256>>>(h, b_in, b_tau, gamma, beta, out_h, out_tau);
}